// round 8
// baseline (speedup 1.0000x reference)
#include <cuda_runtime.h>
#include <cuda_bf16.h>
#include <cstdint>

// Problem constants
#define NB     64
#define OC     128
#define BATCH  4
#define TLEN   1024
#define FBINS  1025
#define TM     128     // t rows per CTA
#define KC     32      // K per smem buffer (2 x m16n8k16 steps)
#define XN     8396800 // BATCH*2*TLEN*FBINS

// Smem: 4 tiles per buffer, 128 rows x 80B (64B data = 32 bf16 + 16B pad).
// RSTR=80: 16B-aligned rows, ldmatrix conflict-free (20r mod 32 distinct).
#define RSTR   80
#define TSZ    10240            // 128*80
#define BUFSZ  40960            // 4 tiles
#define T_AH   0
#define T_AL   10240
#define T_BH   20480
#define T_BL   30720
#define SM_IDX 81920            // int[192]
#define SM_BIAS 82688           // float[128]
#define SM_BYTES 83200

// Device scratch
__device__ float          g_scr[NB * BATCH * TLEN * OC];  // (k,b,t,o)
__device__ unsigned short g_xh[XN];                        // x hi bf16, x-layout
__device__ unsigned short g_xl[XN];                        // x lo bf16
__device__ unsigned       g_bh32[NB * OC * 256];           // B' hi bf16 [k][o][kkpad]
__device__ unsigned       g_bl32[NB * OC * 256];           // B' lo

typedef unsigned u32;
typedef unsigned long long u64;

__device__ __forceinline__ u32 smem_u32(const void* p) {
    u32 a;
    asm("{ .reg .u64 t; cvta.to.shared.u64 t, %1; cvt.u32.u64 %0, t; }" : "=r"(a) : "l"(p));
    return a;
}
__device__ __forceinline__ void cp16(u32 dst, const void* src) {
    asm volatile("cp.async.cg.shared.global [%0], [%1], 16;" :: "r"(dst), "l"(src) : "memory");
}
__device__ __forceinline__ void cp_commit() { asm volatile("cp.async.commit_group;" ::: "memory"); }
__device__ __forceinline__ void cp_wait0()  { asm volatile("cp.async.wait_group 0;" ::: "memory"); }

#define LDX4(r, addr) \
    asm volatile("ldmatrix.sync.aligned.m8n8.x4.shared.b16 {%0,%1,%2,%3}, [%4];" \
        : "=r"((r)[0]), "=r"((r)[1]), "=r"((r)[2]), "=r"((r)[3]) : "r"(addr))

#define MMA(d, A, b0, b1) \
    asm volatile("mma.sync.aligned.m16n8k16.row.col.f32.bf16.bf16.f32 " \
        "{%0,%1,%2,%3}, {%4,%5,%6,%7}, {%8,%9}, {%0,%1,%2,%3};" \
        : "+f"((d)[0]), "+f"((d)[1]), "+f"((d)[2]), "+f"((d)[3]) \
        : "r"((A)[0]), "r"((A)[1]), "r"((A)[2]), "r"((A)[3]), "r"(b0), "r"(b1))

__device__ __forceinline__ unsigned short bf16hi(float v) {
    return __bfloat16_as_ushort(__float2bfloat16_rn(v));
}
__device__ __forceinline__ float bf2f(unsigned short h) {
    return __uint_as_float(((u32)h) << 16);
}

// ---------------------------------------------------------------------------
// split_x: x (fp32) -> g_xh/g_xl bf16 (hi + residual), same layout. Pure BW.
// ---------------------------------------------------------------------------
__global__ __launch_bounds__(256) void split_x(const float* __restrict__ x) {
    size_t base = ((size_t)blockIdx.x * 256 + threadIdx.x) * 8;
    float4 v0 = *(const float4*)(x + base);
    float4 v1 = *(const float4*)(x + base + 4);
    float vv[8] = {v0.x, v0.y, v0.z, v0.w, v1.x, v1.y, v1.z, v1.w};
    unsigned short h[8], l[8];
#pragma unroll
    for (int i = 0; i < 8; i++) {
        h[i] = bf16hi(vv[i]);
        l[i] = bf16hi(vv[i] - bf2f(h[i]));
    }
    u64 H0 = (u64)h[0] | ((u64)h[1] << 16) | ((u64)h[2] << 32) | ((u64)h[3] << 48);
    u64 H1 = (u64)h[4] | ((u64)h[5] << 16) | ((u64)h[6] << 32) | ((u64)h[7] << 48);
    u64 L0 = (u64)l[0] | ((u64)l[1] << 16) | ((u64)l[2] << 32) | ((u64)l[3] << 48);
    u64 L1 = (u64)l[4] | ((u64)l[5] << 16) | ((u64)l[6] << 32) | ((u64)l[7] << 48);
    *(u64*)(g_xh + base) = H0; *(u64*)(g_xh + base + 4) = H1;
    *(u64*)(g_xl + base) = L0; *(u64*)(g_xl + base + 4) = L1;
}

// ---------------------------------------------------------------------------
// prepB: B'[k][o][kk] = split(mel[k][w] * pre_w[k][c][w][o]),  kk = c*W + w.
// 32kk x 128o tiles, grid (KKPAD/32, NB) for full-chip occupancy.
// ---------------------------------------------------------------------------
__global__ __launch_bounds__(256) void prepB(const float* __restrict__ pre_w,
                                             const float* __restrict__ mel_w,
                                             int W, int KTOT, int KKPAD) {
    __shared__ float tile[32][129];
    int ch = blockIdx.x, k = blockIdx.y, tid = threadIdx.x;
#pragma unroll
    for (int i = 0; i < 16; i++) {
        int e = tid + i * 256;             // 0..4095
        int kkL = e >> 7, o = e & 127;
        int kkg = ch * 32 + kkL;
        float v = 0.f;
        if (kkg < KTOT) {
            int c = (kkg >= W), w = kkg - (c ? W : 0);
            v = mel_w[k * W + w] * pre_w[((size_t)(k * 2 + c) * W + w) * OC + o];
        }
        tile[kkL][o] = v;
    }
    __syncthreads();
    unsigned short* bh = (unsigned short*)g_bh32;
    unsigned short* bl = (unsigned short*)g_bl32;
#pragma unroll
    for (int i = 0; i < 16; i++) {
        int e = tid + i * 256;
        int o = e >> 5, kkL = e & 31;
        float v = tile[kkL][o];
        unsigned short h = bf16hi(v);
        unsigned short l = bf16hi(v - bf2f(h));
        size_t d = (size_t)(k * OC + o) * KKPAD + ch * 32 + kkL;
        bh[d] = h; bl[d] = l;
    }
}

// ---------------------------------------------------------------------------
// Tensor-core band GEMM: 3-term bf16 split, KC=32 chunks, ONE barrier/chunk.
// CTA (k, b, t-tile 128); 8 warps 4x2; warp tile 32x64.
// A path is a pure copy (x pre-split), B via cp.async (mel pre-folded).
// ---------------------------------------------------------------------------
__global__ __launch_bounds__(256, 2) void gemm_mma(
    const int* __restrict__ idx, const float* __restrict__ bias,
    int W, int KTOT, int nChunks, int KKPAD) {
    extern __shared__ char smem[];
    const u32 sb = smem_u32(smem);
    const int tid = threadIdx.x, wid = tid >> 5, lane = tid & 31;
    const int k = blockIdx.z, b = blockIdx.y, t0 = blockIdx.x * TM;
    const int wm = wid >> 1, wn = wid & 1;
    const int mbase = wm * 32, nbase = wn * 64;

    int*   idx_s  = (int*)(smem + SM_IDX);
    float* bias_s = (float*)(smem + SM_BIAS);
    for (int e = tid; e < W; e += 256) idx_s[e] = idx[k * W + e];
    if (tid < 128) bias_s[tid] = bias[k * OC + tid];
    __syncthreads();

    // --- A copy path: thread owns col pair (2pr, 2pr+1), rows r0+16i ---
    const int pr = tid & 15;
    const int r0 = tid >> 4;
    u32 ahR[8], alR[8];
    auto loadA = [&](int ch) {
        int ke0 = ch * KC + 2 * pr, ke1 = ke0 + 1;
        int c0 = 0, f0 = 0, c1 = 0, f1 = 0;
        if (ke0 < KTOT) { c0 = (ke0 >= W); f0 = idx_s[ke0 - (c0 ? W : 0)]; }
        if (ke1 < KTOT) { c1 = (ke1 >= W); f1 = idx_s[ke1 - (c1 ? W : 0)]; }
        size_t o0 = ((size_t)(b * 2 + c0) * TLEN + t0 + r0) * FBINS + f0;
        size_t o1 = ((size_t)(b * 2 + c1) * TLEN + t0 + r0) * FBINS + f1;
#pragma unroll
        for (int i = 0; i < 8; i++) {
            size_t s = (size_t)i * 16 * FBINS;
            u32 h0 = g_xh[o0 + s], h1 = g_xh[o1 + s];
            u32 l0 = g_xl[o0 + s], l1 = g_xl[o1 + s];
            ahR[i] = h0 | (h1 << 16);
            alR[i] = l0 | (l1 << 16);
        }
    };
    auto stsA = [&](u32 off) {
#pragma unroll
        for (int i = 0; i < 8; i++) {
            u32 ba = off + (u32)(r0 + 16 * i) * RSTR + (u32)pr * 4;
            *(u32*)(smem + ba + T_AH) = ahR[i];
            *(u32*)(smem + ba + T_AL) = alR[i];
        }
    };
    // --- B: 4x cp.async 16B per thread per chunk ---
    const int oB = tid >> 1, segB = tid & 1;
    const size_t brow = (size_t)(k * OC + oB) * (KKPAD >> 1);
    auto issueB = [&](int ch, u32 off) {
        const u32* srcH = g_bh32 + brow + ch * 16 + segB * 8;
        const u32* srcL = g_bl32 + brow + ch * 16 + segB * 8;
        u32 dst = sb + off + (u32)oB * RSTR + (u32)segB * 32;
        cp16(dst + T_BH, srcH);     cp16(dst + T_BH + 16, srcH + 4);
        cp16(dst + T_BL, srcL);     cp16(dst + T_BL + 16, srcL + 4);
        cp_commit();
    };

    float acc[2][8][4];
#pragma unroll
    for (int mt = 0; mt < 2; mt++)
#pragma unroll
        for (int nt = 0; nt < 8; nt++)
#pragma unroll
            for (int j = 0; j < 4; j++) acc[mt][nt][j] = 0.f;

    issueB(0, 0);
    loadA(0);

    for (int ch = 0; ch < nChunks; ch++) {
        const u32 off = (u32)(ch & 1) * BUFSZ;
        stsA(off);
        cp_wait0();
        __syncthreads();                   // single barrier per chunk
        if (ch + 1 < nChunks) { issueB(ch + 1, off ^ BUFSZ); loadA(ch + 1); }

#pragma unroll
        for (int ks = 0; ks < 2; ks++) {
            u32 ah[2][4], al[2][4];
#pragma unroll
            for (int mt = 0; mt < 2; mt++) {
                u32 aaddr = sb + off + (u32)(mbase + mt * 16 + (lane & 15)) * RSTR
                          + (u32)ks * 32 + ((u32)(lane >> 4) << 4);
                LDX4(ah[mt], aaddr + T_AH);
                LDX4(al[mt], aaddr + T_AL);
            }
#pragma unroll
            for (int np = 0; np < 4; np++) {
                int rn = nbase + np * 16 + (lane & 7) + ((lane >> 1) & 8);
                u32 baddr = sb + off + (u32)rn * RSTR + (u32)ks * 32
                          + (((u32)(lane >> 3) & 1) << 4);
                u32 bh[4], bl[4];
                LDX4(bh, baddr + T_BH);
                LDX4(bl, baddr + T_BL);
#pragma unroll
                for (int h = 0; h < 2; h++) {
                    int nt = np * 2 + h;
#pragma unroll
                    for (int mt = 0; mt < 2; mt++) {
                        MMA(acc[mt][nt], ah[mt], bh[2 * h], bh[2 * h + 1]);
                        MMA(acc[mt][nt], al[mt], bh[2 * h], bh[2 * h + 1]);
                        MMA(acc[mt][nt], ah[mt], bl[2 * h], bl[2 * h + 1]);
                    }
                }
            }
        }
        // trailing barrier removed: stsA(ch+1) targets the other buffer, whose
        // readers all passed this chunk's barrier after finishing compute(ch-1).
    }

    // Epilogue: bias + store (k,b,t,o)
#pragma unroll
    for (int mt = 0; mt < 2; mt++) {
        int m0 = mbase + mt * 16 + (lane >> 2);
        float* base0 = g_scr + ((size_t)(k * BATCH + b) * TLEN + t0 + m0) * OC;
        float* base1 = base0 + 8 * OC;
#pragma unroll
        for (int nt = 0; nt < 8; nt++) {
            int o0 = nbase + nt * 8 + (lane & 3) * 2;
            float2 bb = *(float2*)(bias_s + o0);
            float2 v0, v1;
            v0.x = acc[mt][nt][0] + bb.x; v0.y = acc[mt][nt][1] + bb.y;
            v1.x = acc[mt][nt][2] + bb.x; v1.y = acc[mt][nt][3] + bb.y;
            *(float2*)(base0 + o0) = v0;
            *(float2*)(base1 + o0) = v1;
        }
    }
}

// ---------------------------------------------------------------------------
// Transpose (k,b,t,o) -> (b,o,t,k)
// ---------------------------------------------------------------------------
__global__ __launch_bounds__(256) void trans_kernel(float* __restrict__ out) {
    __shared__ float sm[NB][OC + 1];
    int t = blockIdx.x, b = blockIdx.y, tid = threadIdx.x;
    const float* src = g_scr + ((size_t)b * TLEN + t) * OC;
#pragma unroll
    for (int i = 0; i < 32; i++) {
        int e = tid + i * 256;
        int kk = e >> 7, o = e & 127;
        sm[kk][o] = src[(size_t)kk * (BATCH * TLEN * OC) + o];
    }
    __syncthreads();
    float* dst = out + ((size_t)b * OC) * (TLEN * (size_t)NB) + (size_t)t * NB;
#pragma unroll
    for (int i = 0; i < 32; i++) {
        int e = tid + i * 256;
        int o = e >> 6, kk = e & 63;
        dst[(size_t)o * (TLEN * NB) + kk] = sm[kk][o];
    }
}

// ---------------------------------------------------------------------------
extern "C" void kernel_launch(void* const* d_in, const int* in_sizes, int n_in,
                              void* d_out, int out_size) {
    const float* x     = (const float*)d_in[0];
    const int*   idx   = (const int*)  d_in[1];
    const float* mel_w = (const float*)d_in[2];
    const float* pre_w = (const float*)d_in[3];
    const float* pre_b = (const float*)d_in[4];
    float* out = (float*)d_out;

    int W = in_sizes[1] / NB;
    int KTOT = 2 * W;
    int nCh = (KTOT + KC - 1) / KC;
    int KKPAD = nCh * KC;

    cudaFuncSetAttribute(gemm_mma, cudaFuncAttributeMaxDynamicSharedMemorySize, SM_BYTES);

    split_x<<<XN / 2048, 256>>>(x);
    prepB<<<dim3(nCh * (KC / 32), NB), 256>>>(pre_w, mel_w, W, KTOT, KKPAD);
    gemm_mma<<<dim3(TLEN / TM, BATCH, NB), 256, SM_BYTES>>>(idx, pre_b, W, KTOT, nCh, KKPAD);
    trans_kernel<<<dim3(TLEN, BATCH), 256>>>(out);
}

// round 10
// speedup vs baseline: 1.1280x; 1.1280x over previous
#include <cuda_runtime.h>
#include <cuda_bf16.h>
#include <cstdint>

// Problem constants
#define NB     64
#define OC     128
#define BATCH  4
#define TLEN   1024
#define FBINS  1025
#define TM     128     // t rows per CTA
#define KC     32      // K per smem buffer (2 x m16n8k16 steps)

// Smem: 4 tiles per buffer, 128 rows x 80B (64B data = 32 bf16 + 16B pad).
// RSTR=80: 16B-aligned rows, ldmatrix conflict-free (20r mod 32 distinct).
#define RSTR   80
#define BUFSZ  40960            // 4 tiles x 128 x 80
#define T_AH   0
#define T_AL   10240
#define T_BH   20480
#define T_BL   30720
#define SM_IDX 81920            // int[192]
#define SM_BIAS 82688           // float[128]
#define SM_BYTES 83200

// Device scratch
__device__ float    g_scr[NB * BATCH * TLEN * OC];  // (k,b,t,o)
__device__ unsigned g_bh32[NB * OC * 256];          // B' hi bf16 [k][o][kkpad]
__device__ unsigned g_bl32[NB * OC * 256];          // B' lo

typedef unsigned u32;

__device__ __forceinline__ u32 smem_u32(const void* p) {
    u32 a;
    asm("{ .reg .u64 t; cvta.to.shared.u64 t, %1; cvt.u32.u64 %0, t; }" : "=r"(a) : "l"(p));
    return a;
}
__device__ __forceinline__ void cp16(u32 dst, const void* src) {
    asm volatile("cp.async.cg.shared.global [%0], [%1], 16;" :: "r"(dst), "l"(src) : "memory");
}
__device__ __forceinline__ void cp_commit() { asm volatile("cp.async.commit_group;" ::: "memory"); }
__device__ __forceinline__ void cp_wait0()  { asm volatile("cp.async.wait_group 0;" ::: "memory"); }

#define LDX4(r, addr) \
    asm volatile("ldmatrix.sync.aligned.m8n8.x4.shared.b16 {%0,%1,%2,%3}, [%4];" \
        : "=r"((r)[0]), "=r"((r)[1]), "=r"((r)[2]), "=r"((r)[3]) : "r"(addr))

#define MMA(d, A, b0, b1) \
    asm volatile("mma.sync.aligned.m16n8k16.row.col.f32.bf16.bf16.f32 " \
        "{%0,%1,%2,%3}, {%4,%5,%6,%7}, {%8,%9}, {%0,%1,%2,%3};" \
        : "+f"((d)[0]), "+f"((d)[1]), "+f"((d)[2]), "+f"((d)[3]) \
        : "r"((A)[0]), "r"((A)[1]), "r"((A)[2]), "r"((A)[3]), "r"(b0), "r"(b1))

__device__ __forceinline__ unsigned short bf16hi(float v) {
    return __bfloat16_as_ushort(__float2bfloat16_rn(v));
}
__device__ __forceinline__ float bf2f(unsigned short h) {
    return __uint_as_float(((u32)h) << 16);
}
// split one fp32 -> (hi, lo) bf16 pair
__device__ __forceinline__ void split2(float v, unsigned short& h, unsigned short& l) {
    h = bf16hi(v);
    l = bf16hi(v - bf2f(h));
}

// ---------------------------------------------------------------------------
// prepB: B'[k][o][kk] = split(mel[k][w] * pre_w[k][c][w][o]),  kk = c*W + w.
// 32kk x 128o tiles, grid (nCh, NB); zero-fills padded kk.
// ---------------------------------------------------------------------------
__global__ __launch_bounds__(256) void prepB(const float* __restrict__ pre_w,
                                             const float* __restrict__ mel_w,
                                             int W, int KTOT, int KKPAD) {
    __shared__ float tile[32][129];
    int ch = blockIdx.x, k = blockIdx.y, tid = threadIdx.x;
#pragma unroll
    for (int i = 0; i < 16; i++) {
        int e = tid + i * 256;
        int kkL = e >> 7, o = e & 127;
        int kkg = ch * 32 + kkL;
        float v = 0.f;
        if (kkg < KTOT) {
            int c = (kkg >= W), w = kkg - (c ? W : 0);
            v = mel_w[k * W + w] * pre_w[((size_t)(k * 2 + c) * W + w) * OC + o];
        }
        tile[kkL][o] = v;
    }
    __syncthreads();
    unsigned short* bh = (unsigned short*)g_bh32;
    unsigned short* bl = (unsigned short*)g_bl32;
#pragma unroll
    for (int i = 0; i < 16; i++) {
        int e = tid + i * 256;
        int o = e >> 5, kkL = e & 31;
        unsigned short h, l;
        split2(tile[kkL][o], h, l);
        size_t d = (size_t)(k * OC + o) * KKPAD + ch * 32 + kkL;
        bh[d] = h; bl[d] = l;
    }
}

// ---------------------------------------------------------------------------
// Tensor-core band GEMM: 3-term bf16 split (AhBh + AlBh + AhBl).
// CTA (k, b, t-tile 128); 8 warps 4x2; warp tile 32x64; KC=32, 1 barrier/chunk.
// A: fp32 x loads (wide, L2-resident) + in-register split, overlapped w/ MMA.
// B: pre-split + mel-folded, via cp.async.
// ---------------------------------------------------------------------------
__global__ __launch_bounds__(256, 2) void gemm_mma(
    const float* __restrict__ x, const int* __restrict__ idx,
    const float* __restrict__ bias, int W, int KTOT, int nChunks, int KKPAD) {
    extern __shared__ char smem[];
    const u32 sb = smem_u32(smem);
    const int tid = threadIdx.x, wid = tid >> 5, lane = tid & 31;
    const int k = blockIdx.z, b = blockIdx.y, t0 = blockIdx.x * TM;
    const int wm = wid >> 1, wn = wid & 1;
    const int mbase = wm * 32, nbase = wn * 64;

    int*   idx_s  = (int*)(smem + SM_IDX);
    float* bias_s = (float*)(smem + SM_BIAS);
    for (int e = tid; e < W; e += 256) idx_s[e] = idx[k * W + e];
    if (tid < 128) bias_s[tid] = bias[k * OC + tid];
    __syncthreads();

    const float* xb = x + (size_t)b * 2 * TLEN * FBINS;

    // --- A: thread owns col pair (2pr, 2pr+1), rows r0+16i; packed hi/lo u32 ---
    const int pr = tid & 15;
    const int r0 = tid >> 4;
    u32 ahR[8], alR[8];
    auto loadA = [&](int ch) {
        int ke0 = ch * KC + 2 * pr, ke1 = ke0 + 1;
        int c0 = 0, f0 = 0, c1 = 0, f1 = 0;
        if (ke0 < KTOT) { c0 = (ke0 >= W); f0 = idx_s[ke0 - (c0 ? W : 0)]; }
        if (ke1 < KTOT) { c1 = (ke1 >= W); f1 = idx_s[ke1 - (c1 ? W : 0)]; }
        const float* p0 = xb + (size_t)(c0 * TLEN + t0 + r0) * FBINS + f0;
        const float* p1 = xb + (size_t)(c1 * TLEN + t0 + r0) * FBINS + f1;
#pragma unroll
        for (int i = 0; i < 8; i++) {
            size_t s = (size_t)i * 16 * FBINS;
            float v0 = p0[s], v1 = p1[s];      // wide LDG.32, coalesced over lanes
            unsigned short h0, l0, h1, l1;
            split2(v0, h0, l0);
            split2(v1, h1, l1);
            ahR[i] = (u32)h0 | ((u32)h1 << 16);
            alR[i] = (u32)l0 | ((u32)l1 << 16);
        }
    };
    auto stsA = [&](u32 off) {
#pragma unroll
        for (int i = 0; i < 8; i++) {
            u32 ba = off + (u32)(r0 + 16 * i) * RSTR + (u32)pr * 4;
            *(u32*)(smem + ba + T_AH) = ahR[i];
            *(u32*)(smem + ba + T_AL) = alR[i];
        }
    };
    // --- B: 4x cp.async 16B per thread per chunk ---
    const int oB = tid >> 1, segB = tid & 1;
    const size_t brow = (size_t)(k * OC + oB) * (KKPAD >> 1);
    auto issueB = [&](int ch, u32 off) {
        const u32* srcH = g_bh32 + brow + ch * 16 + segB * 8;
        const u32* srcL = g_bl32 + brow + ch * 16 + segB * 8;
        u32 dst = sb + off + (u32)oB * RSTR + (u32)segB * 32;
        cp16(dst + T_BH, srcH);     cp16(dst + T_BH + 16, srcH + 4);
        cp16(dst + T_BL, srcL);     cp16(dst + T_BL + 16, srcL + 4);
        cp_commit();
    };

    float acc[2][8][4];
#pragma unroll
    for (int mt = 0; mt < 2; mt++)
#pragma unroll
        for (int nt = 0; nt < 8; nt++)
#pragma unroll
            for (int j = 0; j < 4; j++) acc[mt][nt][j] = 0.f;

    issueB(0, 0);
    loadA(0);

    for (int ch = 0; ch < nChunks; ch++) {
        const u32 off = (u32)(ch & 1) * BUFSZ;
        stsA(off);
        cp_wait0();
        __syncthreads();                   // single barrier per chunk
        if (ch + 1 < nChunks) { issueB(ch + 1, off ^ BUFSZ); loadA(ch + 1); }

#pragma unroll
        for (int ks = 0; ks < 2; ks++) {
            u32 ah[2][4], al[2][4];
#pragma unroll
            for (int mt = 0; mt < 2; mt++) {
                u32 aaddr = sb + off + (u32)(mbase + mt * 16 + (lane & 15)) * RSTR
                          + (u32)ks * 32 + ((u32)(lane >> 4) << 4);
                LDX4(ah[mt], aaddr + T_AH);
                LDX4(al[mt], aaddr + T_AL);
            }
#pragma unroll
            for (int np = 0; np < 4; np++) {
                int rn = nbase + np * 16 + (lane & 7) + ((lane >> 1) & 8);
                u32 baddr = sb + off + (u32)rn * RSTR + (u32)ks * 32
                          + (((u32)(lane >> 3) & 1) << 4);
                u32 bh[4], bl[4];
                LDX4(bh, baddr + T_BH);
                LDX4(bl, baddr + T_BL);
#pragma unroll
                for (int h = 0; h < 2; h++) {
                    int nt = np * 2 + h;
#pragma unroll
                    for (int mt = 0; mt < 2; mt++) {
                        MMA(acc[mt][nt], ah[mt], bh[2 * h], bh[2 * h + 1]);
                        MMA(acc[mt][nt], al[mt], bh[2 * h], bh[2 * h + 1]);
                        MMA(acc[mt][nt], ah[mt], bl[2 * h], bl[2 * h + 1]);
                    }
                }
            }
        }
        // trailing barrier elided: next stsA targets the other buffer, whose
        // readers all passed this chunk's barrier after finishing its compute.
    }

    // Epilogue: bias + store (k,b,t,o)
#pragma unroll
    for (int mt = 0; mt < 2; mt++) {
        int m0 = mbase + mt * 16 + (lane >> 2);
        float* base0 = g_scr + ((size_t)(k * BATCH + b) * TLEN + t0 + m0) * OC;
        float* base1 = base0 + 8 * OC;
#pragma unroll
        for (int nt = 0; nt < 8; nt++) {
            int o0 = nbase + nt * 8 + (lane & 3) * 2;
            float2 bb = *(float2*)(bias_s + o0);
            float2 v0, v1;
            v0.x = acc[mt][nt][0] + bb.x; v0.y = acc[mt][nt][1] + bb.y;
            v1.x = acc[mt][nt][2] + bb.x; v1.y = acc[mt][nt][3] + bb.y;
            *(float2*)(base0 + o0) = v0;
            *(float2*)(base1 + o0) = v1;
        }
    }
}

// ---------------------------------------------------------------------------
// Transpose (k,b,t,o) -> (b,o,t,k)
// ---------------------------------------------------------------------------
__global__ __launch_bounds__(256) void trans_kernel(float* __restrict__ out) {
    __shared__ float sm[NB][OC + 1];
    int t = blockIdx.x, b = blockIdx.y, tid = threadIdx.x;
    const float* src = g_scr + ((size_t)b * TLEN + t) * OC;
#pragma unroll
    for (int i = 0; i < 32; i++) {
        int e = tid + i * 256;
        int kk = e >> 7, o = e & 127;
        sm[kk][o] = src[(size_t)kk * (BATCH * TLEN * OC) + o];
    }
    __syncthreads();
    float* dst = out + ((size_t)b * OC) * (TLEN * (size_t)NB) + (size_t)t * NB;
#pragma unroll
    for (int i = 0; i < 32; i++) {
        int e = tid + i * 256;
        int o = e >> 6, kk = e & 63;
        dst[(size_t)o * (TLEN * NB) + kk] = sm[kk][o];
    }
}

// ---------------------------------------------------------------------------
extern "C" void kernel_launch(void* const* d_in, const int* in_sizes, int n_in,
                              void* d_out, int out_size) {
    const float* x     = (const float*)d_in[0];
    const int*   idx   = (const int*)  d_in[1];
    const float* mel_w = (const float*)d_in[2];
    const float* pre_w = (const float*)d_in[3];
    const float* pre_b = (const float*)d_in[4];
    float* out = (float*)d_out;

    int W = in_sizes[1] / NB;
    int KTOT = 2 * W;
    int nCh = (KTOT + KC - 1) / KC;
    int KKPAD = nCh * KC;

    cudaFuncSetAttribute(gemm_mma, cudaFuncAttributeMaxDynamicSharedMemorySize, SM_BYTES);

    prepB<<<dim3(nCh, NB), 256>>>(pre_w, mel_w, W, KTOT, KKPAD);
    gemm_mma<<<dim3(TLEN / TM, BATCH, NB), 256, SM_BYTES>>>(x, idx, pre_b,
                                                            W, KTOT, nCh, KKPAD);
    trans_kernel<<<dim3(TLEN, BATCH), 256>>>(out);
}

// round 11
// speedup vs baseline: 1.3822x; 1.2254x over previous
#include <cuda_runtime.h>
#include <cuda_fp16.h>
#include <cstdint>

// Problem constants
#define NB     64
#define OC     128
#define BATCH  4
#define TLEN   1024
#define FBINS  1025
#define TM     128     // t rows per CTA
#define KC     32      // K per smem buffer (2 x m16n8k16 steps)

// Smem: 3 tiles per buffer (AH, AL, BH), 128 rows x 80B (64B data + 16B pad).
// RSTR=80: 16B-aligned rows, ldmatrix conflict-free (20r mod 32 distinct).
#define RSTR   80
#define BUFSZ  30720            // 3 tiles x 128 x 80
#define T_AH   0
#define T_AL   10240
#define T_BH   20480
#define SM_IDX 61440            // int[192]
#define SM_BIAS 62208           // float[128]
#define SM_BYTES 62720

// Device scratch
__device__ float    g_scr[NB * BATCH * TLEN * OC];  // (k,b,t,o)
__device__ unsigned g_b16[NB * OC * 256];           // B' fp16 [k][o][kkpad], u32 pairs

typedef unsigned u32;

__device__ __forceinline__ u32 smem_u32(const void* p) {
    u32 a;
    asm("{ .reg .u64 t; cvta.to.shared.u64 t, %1; cvt.u32.u64 %0, t; }" : "=r"(a) : "l"(p));
    return a;
}
__device__ __forceinline__ void cp16(u32 dst, const void* src) {
    asm volatile("cp.async.cg.shared.global [%0], [%1], 16;" :: "r"(dst), "l"(src) : "memory");
}
__device__ __forceinline__ void cp_commit() { asm volatile("cp.async.commit_group;" ::: "memory"); }
__device__ __forceinline__ void cp_wait0()  { asm volatile("cp.async.wait_group 0;" ::: "memory"); }

#define LDX4(r, addr) \
    asm volatile("ldmatrix.sync.aligned.m8n8.x4.shared.b16 {%0,%1,%2,%3}, [%4];" \
        : "=r"((r)[0]), "=r"((r)[1]), "=r"((r)[2]), "=r"((r)[3]) : "r"(addr))

#define MMA(d, A, b0, b1) \
    asm volatile("mma.sync.aligned.m16n8k16.row.col.f32.f16.f16.f32 " \
        "{%0,%1,%2,%3}, {%4,%5,%6,%7}, {%8,%9}, {%0,%1,%2,%3};" \
        : "+f"((d)[0]), "+f"((d)[1]), "+f"((d)[2]), "+f"((d)[3]) \
        : "r"((A)[0]), "r"((A)[1]), "r"((A)[2]), "r"((A)[3]), "r"(b0), "r"(b1))

// fp16 2-term split: v = hi + lo with |lo| <~ 2^-11 |v|, combined exact to ~2^-22
__device__ __forceinline__ void split2h(float v, unsigned short& h, unsigned short& l) {
    __half hh = __float2half_rn(v);
    h = __half_as_ushort(hh);
    l = __half_as_ushort(__float2half_rn(v - __half2float(hh)));
}

// ---------------------------------------------------------------------------
// prepB: B'[k][o][kk] = fp16(mel[k][w] * pre_w[k][c][w][o]),  kk = c*W + w.
// 32kk x 128o tiles, grid (nCh, NB); zero-fills padded kk.
// ---------------------------------------------------------------------------
__global__ __launch_bounds__(256) void prepB(const float* __restrict__ pre_w,
                                             const float* __restrict__ mel_w,
                                             int W, int KTOT, int KKPAD) {
    __shared__ float tile[32][129];
    int ch = blockIdx.x, k = blockIdx.y, tid = threadIdx.x;
#pragma unroll
    for (int i = 0; i < 16; i++) {
        int e = tid + i * 256;
        int kkL = e >> 7, o = e & 127;
        int kkg = ch * 32 + kkL;
        float v = 0.f;
        if (kkg < KTOT) {
            int c = (kkg >= W), w = kkg - (c ? W : 0);
            v = mel_w[k * W + w] * pre_w[((size_t)(k * 2 + c) * W + w) * OC + o];
        }
        tile[kkL][o] = v;
    }
    __syncthreads();
    unsigned short* bp = (unsigned short*)g_b16;
#pragma unroll
    for (int i = 0; i < 16; i++) {
        int e = tid + i * 256;
        int o = e >> 5, kkL = e & 31;
        bp[(size_t)(k * OC + o) * KKPAD + ch * 32 + kkL] =
            __half_as_ushort(__float2half_rn(tile[kkL][o]));
    }
}

// ---------------------------------------------------------------------------
// Tensor-core band GEMM, fp16x2: D = Ah*B + Al*B  (A hi/lo fp16, B fp16).
// CTA (k, b, t-tile 128); 8 warps 4x2; warp tile 32x64; KC=32, 1 barrier/chunk.
// A: fp32 x loads (L2-resident) + in-register split, overlapped with MMA.
// B: pre-converted + mel-folded, via cp.async.
// ---------------------------------------------------------------------------
__global__ __launch_bounds__(256, 2) void gemm_mma(
    const float* __restrict__ x, const int* __restrict__ idx,
    const float* __restrict__ bias, int W, int KTOT, int nChunks, int KKPAD) {
    extern __shared__ char smem[];
    const u32 sb = smem_u32(smem);
    const int tid = threadIdx.x, wid = tid >> 5, lane = tid & 31;
    const int k = blockIdx.z, b = blockIdx.y, t0 = blockIdx.x * TM;
    const int wm = wid >> 1, wn = wid & 1;
    const int mbase = wm * 32, nbase = wn * 64;

    int*   idx_s  = (int*)(smem + SM_IDX);
    float* bias_s = (float*)(smem + SM_BIAS);
    for (int e = tid; e < W; e += 256) idx_s[e] = idx[k * W + e];
    if (tid < 128) bias_s[tid] = bias[k * OC + tid];
    __syncthreads();

    const float* xb = x + (size_t)b * 2 * TLEN * FBINS;

    // --- A: thread owns col pair (2pr, 2pr+1), rows r0+16i; packed hi/lo u32 ---
    const int pr = tid & 15;
    const int r0 = tid >> 4;
    u32 ahR[8], alR[8];
    auto loadA = [&](int ch) {
        int ke0 = ch * KC + 2 * pr, ke1 = ke0 + 1;
        int c0 = 0, f0 = 0, c1 = 0, f1 = 0;
        if (ke0 < KTOT) { c0 = (ke0 >= W); f0 = idx_s[ke0 - (c0 ? W : 0)]; }
        if (ke1 < KTOT) { c1 = (ke1 >= W); f1 = idx_s[ke1 - (c1 ? W : 0)]; }
        const float* p0 = xb + (size_t)(c0 * TLEN + t0 + r0) * FBINS + f0;
        const float* p1 = xb + (size_t)(c1 * TLEN + t0 + r0) * FBINS + f1;
#pragma unroll
        for (int i = 0; i < 8; i++) {
            size_t s = (size_t)i * 16 * FBINS;
            float v0 = p0[s], v1 = p1[s];      // wide LDG.32, coalesced over lanes
            unsigned short h0, l0, h1, l1;
            split2h(v0, h0, l0);
            split2h(v1, h1, l1);
            ahR[i] = (u32)h0 | ((u32)h1 << 16);
            alR[i] = (u32)l0 | ((u32)l1 << 16);
        }
    };
    auto stsA = [&](u32 off) {
#pragma unroll
        for (int i = 0; i < 8; i++) {
            u32 ba = off + (u32)(r0 + 16 * i) * RSTR + (u32)pr * 4;
            *(u32*)(smem + ba + T_AH) = ahR[i];
            *(u32*)(smem + ba + T_AL) = alR[i];
        }
    };
    // --- B: 2x cp.async 16B per thread per chunk ---
    const int oB = tid >> 1, segB = tid & 1;
    const size_t brow = (size_t)(k * OC + oB) * (KKPAD >> 1);
    auto issueB = [&](int ch, u32 off) {
        const u32* src = g_b16 + brow + ch * 16 + segB * 8;
        u32 dst = sb + off + T_BH + (u32)oB * RSTR + (u32)segB * 32;
        cp16(dst, src);
        cp16(dst + 16, src + 4);
        cp_commit();
    };

    float acc[2][8][4];
#pragma unroll
    for (int mt = 0; mt < 2; mt++)
#pragma unroll
        for (int nt = 0; nt < 8; nt++)
#pragma unroll
            for (int j = 0; j < 4; j++) acc[mt][nt][j] = 0.f;

    issueB(0, 0);
    loadA(0);

    for (int ch = 0; ch < nChunks; ch++) {
        const u32 off = (u32)(ch & 1) * BUFSZ;
        stsA(off);
        cp_wait0();
        __syncthreads();                   // single barrier per chunk
        if (ch + 1 < nChunks) { issueB(ch + 1, off ^ BUFSZ); loadA(ch + 1); }

#pragma unroll
        for (int ks = 0; ks < 2; ks++) {
            u32 ah[2][4], al[2][4];
#pragma unroll
            for (int mt = 0; mt < 2; mt++) {
                u32 aaddr = sb + off + (u32)(mbase + mt * 16 + (lane & 15)) * RSTR
                          + (u32)ks * 32 + ((u32)(lane >> 4) << 4);
                LDX4(ah[mt], aaddr + T_AH);
                LDX4(al[mt], aaddr + T_AL);
            }
#pragma unroll
            for (int np = 0; np < 4; np++) {
                int rn = nbase + np * 16 + (lane & 7) + ((lane >> 1) & 8);
                u32 baddr = sb + off + T_BH + (u32)rn * RSTR + (u32)ks * 32
                          + (((u32)(lane >> 3) & 1) << 4);
                u32 bh[4];
                LDX4(bh, baddr);
#pragma unroll
                for (int h = 0; h < 2; h++) {
                    int nt = np * 2 + h;
#pragma unroll
                    for (int mt = 0; mt < 2; mt++) {
                        MMA(acc[mt][nt], ah[mt], bh[2 * h], bh[2 * h + 1]);
                        MMA(acc[mt][nt], al[mt], bh[2 * h], bh[2 * h + 1]);
                    }
                }
            }
        }
        // trailing barrier elided: next stsA targets the other buffer, whose
        // readers all passed this chunk's barrier after finishing its compute.
    }

    // Epilogue: bias + store (k,b,t,o)
#pragma unroll
    for (int mt = 0; mt < 2; mt++) {
        int m0 = mbase + mt * 16 + (lane >> 2);
        float* base0 = g_scr + ((size_t)(k * BATCH + b) * TLEN + t0 + m0) * OC;
        float* base1 = base0 + 8 * OC;
#pragma unroll
        for (int nt = 0; nt < 8; nt++) {
            int o0 = nbase + nt * 8 + (lane & 3) * 2;
            float2 bb = *(float2*)(bias_s + o0);
            float2 v0, v1;
            v0.x = acc[mt][nt][0] + bb.x; v0.y = acc[mt][nt][1] + bb.y;
            v1.x = acc[mt][nt][2] + bb.x; v1.y = acc[mt][nt][3] + bb.y;
            *(float2*)(base0 + o0) = v0;
            *(float2*)(base1 + o0) = v1;
        }
    }
}

// ---------------------------------------------------------------------------
// Transpose (k,b,t,o) -> (b,o,t,k)
// ---------------------------------------------------------------------------
__global__ __launch_bounds__(256) void trans_kernel(float* __restrict__ out) {
    __shared__ float sm[NB][OC + 1];
    int t = blockIdx.x, b = blockIdx.y, tid = threadIdx.x;
    const float* src = g_scr + ((size_t)b * TLEN + t) * OC;
#pragma unroll
    for (int i = 0; i < 32; i++) {
        int e = tid + i * 256;
        int kk = e >> 7, o = e & 127;
        sm[kk][o] = src[(size_t)kk * (BATCH * TLEN * OC) + o];
    }
    __syncthreads();
    float* dst = out + ((size_t)b * OC) * (TLEN * (size_t)NB) + (size_t)t * NB;
#pragma unroll
    for (int i = 0; i < 32; i++) {
        int e = tid + i * 256;
        int o = e >> 6, kk = e & 63;
        dst[(size_t)o * (TLEN * NB) + kk] = sm[kk][o];
    }
}

// ---------------------------------------------------------------------------
extern "C" void kernel_launch(void* const* d_in, const int* in_sizes, int n_in,
                              void* d_out, int out_size) {
    const float* x     = (const float*)d_in[0];
    const int*   idx   = (const int*)  d_in[1];
    const float* mel_w = (const float*)d_in[2];
    const float* pre_w = (const float*)d_in[3];
    const float* pre_b = (const float*)d_in[4];
    float* out = (float*)d_out;

    int W = in_sizes[1] / NB;
    int KTOT = 2 * W;
    int nCh = (KTOT + KC - 1) / KC;
    int KKPAD = nCh * KC;

    cudaFuncSetAttribute(gemm_mma, cudaFuncAttributeMaxDynamicSharedMemorySize, SM_BYTES);

    prepB<<<dim3(nCh, NB), 256>>>(pre_w, mel_w, W, KTOT, KKPAD);
    gemm_mma<<<dim3(TLEN / TM, BATCH, NB), 256, SM_BYTES>>>(x, idx, pre_b,
                                                            W, KTOT, nCh, KKPAD);
    trans_kernel<<<dim3(TLEN, BATCH), 256>>>(out);
}

// round 13
// speedup vs baseline: 1.6897x; 1.2225x over previous
#include <cuda_runtime.h>
#include <cuda_fp16.h>
#include <cstdint>

// Problem constants
#define NB     64
#define OC     128
#define BATCH  4
#define TLEN   1024
#define FBINS  1025
#define TM     128     // t rows per CTA
#define KC     32      // K per smem buffer (2 x m16n8k16 steps)

// Smem: 2 tiles per buffer (A, B), 128 rows x 80B (64B data + 16B pad).
// RSTR=80: 16B-aligned rows, ldmatrix conflict-free (20r mod 32 distinct).
#define RSTR   80
#define BUFSZ  20480            // 2 tiles x 128 x 80
#define T_A    0
#define T_B    10240
#define SM_IDX 40960            // int[192]
#define SM_BIAS 41728           // float[128]
#define SM_BYTES 42240

// Device scratch
__device__ float    g_scr[NB * BATCH * TLEN * OC];  // (k,b,t,o)
__device__ unsigned g_b16[NB * OC * 256];           // B' fp16 [k][o][kkpad], u32 pairs

typedef unsigned u32;

__device__ __forceinline__ u32 smem_u32(const void* p) {
    u32 a;
    asm("{ .reg .u64 t; cvta.to.shared.u64 t, %1; cvt.u32.u64 %0, t; }" : "=r"(a) : "l"(p));
    return a;
}
__device__ __forceinline__ void cp16(u32 dst, const void* src) {
    asm volatile("cp.async.cg.shared.global [%0], [%1], 16;" :: "r"(dst), "l"(src) : "memory");
}
__device__ __forceinline__ void cp_commit() { asm volatile("cp.async.commit_group;" ::: "memory"); }
__device__ __forceinline__ void cp_wait0()  { asm volatile("cp.async.wait_group 0;" ::: "memory"); }

#define LDX4(r, addr) \
    asm volatile("ldmatrix.sync.aligned.m8n8.x4.shared.b16 {%0,%1,%2,%3}, [%4];" \
        : "=r"((r)[0]), "=r"((r)[1]), "=r"((r)[2]), "=r"((r)[3]) : "r"(addr))

#define MMA(d, A, b0, b1) \
    asm volatile("mma.sync.aligned.m16n8k16.row.col.f32.f16.f16.f32 " \
        "{%0,%1,%2,%3}, {%4,%5,%6,%7}, {%8,%9}, {%0,%1,%2,%3};" \
        : "+f"((d)[0]), "+f"((d)[1]), "+f"((d)[2]), "+f"((d)[3]) \
        : "r"((A)[0]), "r"((A)[1]), "r"((A)[2]), "r"((A)[3]), "r"(b0), "r"(b1))

// ---------------------------------------------------------------------------
// prepB: B'[k][o][kk] = fp16(mel[k][w] * pre_w[k][c][w][o]),  kk = c*W + w.
// 32kk x 128o tiles, grid (nCh, NB); zero-fills padded kk.
// ---------------------------------------------------------------------------
__global__ __launch_bounds__(256) void prepB(const float* __restrict__ pre_w,
                                             const float* __restrict__ mel_w,
                                             int W, int KTOT, int KKPAD) {
    __shared__ float tile[32][129];
    int ch = blockIdx.x, k = blockIdx.y, tid = threadIdx.x;
#pragma unroll
    for (int i = 0; i < 16; i++) {
        int e = tid + i * 256;
        int kkL = e >> 7, o = e & 127;
        int kkg = ch * 32 + kkL;
        float v = 0.f;
        if (kkg < KTOT) {
            int c = (kkg >= W), w = kkg - (c ? W : 0);
            v = mel_w[k * W + w] * pre_w[((size_t)(k * 2 + c) * W + w) * OC + o];
        }
        tile[kkL][o] = v;
    }
    __syncthreads();
    unsigned short* bp = (unsigned short*)g_b16;
#pragma unroll
    for (int i = 0; i < 16; i++) {
        int e = tid + i * 256;
        int o = e >> 5, kkL = e & 31;
        bp[(size_t)(k * OC + o) * KKPAD + ch * 32 + kkL] =
            __half_as_ushort(__float2half_rn(tile[kkL][o]));
    }
}

// ---------------------------------------------------------------------------
// Tensor-core band GEMM, single fp16 term: D = fp16(A) * fp16(mel*W).
// CTA (k, b, t-tile 128); 8 warps 4x2; warp tile 32x64; KC=32, 1 barrier/chunk.
// A: fp32 x loads (L2-resident) + in-register fp16 convert, overlapped w/ MMA.
// B: pre-converted + mel-folded, via cp.async.
// ---------------------------------------------------------------------------
__global__ __launch_bounds__(256, 2) void gemm_mma(
    const float* __restrict__ x, const int* __restrict__ idx,
    const float* __restrict__ bias, int W, int KTOT, int nChunks, int KKPAD) {
    extern __shared__ char smem[];
    const u32 sb = smem_u32(smem);
    const int tid = threadIdx.x, wid = tid >> 5, lane = tid & 31;
    const int k = blockIdx.z, b = blockIdx.y, t0 = blockIdx.x * TM;
    const int wm = wid >> 1, wn = wid & 1;
    const int mbase = wm * 32, nbase = wn * 64;

    int*   idx_s  = (int*)(smem + SM_IDX);
    float* bias_s = (float*)(smem + SM_BIAS);
    for (int e = tid; e < W; e += 256) idx_s[e] = idx[k * W + e];
    if (tid < 128) bias_s[tid] = bias[k * OC + tid];
    __syncthreads();

    const float* xb = x + (size_t)b * 2 * TLEN * FBINS;

    // --- A: thread owns col pair (2pr, 2pr+1), rows r0+16i; packed fp16x2 ---
    const int pr = tid & 15;
    const int r0 = tid >> 4;
    u32 aR[8];
    auto loadA = [&](int ch) {
        int ke0 = ch * KC + 2 * pr, ke1 = ke0 + 1;
        int c0 = 0, f0 = 0, c1 = 0, f1 = 0;
        if (ke0 < KTOT) { c0 = (ke0 >= W); f0 = idx_s[ke0 - (c0 ? W : 0)]; }
        if (ke1 < KTOT) { c1 = (ke1 >= W); f1 = idx_s[ke1 - (c1 ? W : 0)]; }
        const float* p0 = xb + (size_t)(c0 * TLEN + t0 + r0) * FBINS + f0;
        const float* p1 = xb + (size_t)(c1 * TLEN + t0 + r0) * FBINS + f1;
#pragma unroll
        for (int i = 0; i < 8; i++) {
            size_t s = (size_t)i * 16 * FBINS;
            __half2 hv = __floats2half2_rn(p0[s], p1[s]);   // wide LDG.32, coalesced
            aR[i] = *(u32*)&hv;
        }
    };
    auto stsA = [&](u32 off) {
#pragma unroll
        for (int i = 0; i < 8; i++) {
            u32 ba = off + T_A + (u32)(r0 + 16 * i) * RSTR + (u32)pr * 4;
            *(u32*)(smem + ba) = aR[i];
        }
    };
    // --- B: 2x cp.async 16B per thread per chunk ---
    const int oB = tid >> 1, segB = tid & 1;
    const size_t brow = (size_t)(k * OC + oB) * (KKPAD >> 1);
    auto issueB = [&](int ch, u32 off) {
        const u32* src = g_b16 + brow + ch * 16 + segB * 8;
        u32 dst = sb + off + T_B + (u32)oB * RSTR + (u32)segB * 32;
        cp16(dst, src);
        cp16(dst + 16, src + 4);
        cp_commit();
    };

    float acc[2][8][4];
#pragma unroll
    for (int mt = 0; mt < 2; mt++)
#pragma unroll
        for (int nt = 0; nt < 8; nt++)
#pragma unroll
            for (int j = 0; j < 4; j++) acc[mt][nt][j] = 0.f;

    issueB(0, 0);
    loadA(0);

    for (int ch = 0; ch < nChunks; ch++) {
        const u32 off = (u32)(ch & 1) * BUFSZ;
        stsA(off);
        cp_wait0();
        __syncthreads();                   // single barrier per chunk
        if (ch + 1 < nChunks) { issueB(ch + 1, off ^ BUFSZ); loadA(ch + 1); }

#pragma unroll
        for (int ks = 0; ks < 2; ks++) {
            u32 af[2][4];
#pragma unroll
            for (int mt = 0; mt < 2; mt++) {
                u32 aaddr = sb + off + T_A + (u32)(mbase + mt * 16 + (lane & 15)) * RSTR
                          + (u32)ks * 32 + ((u32)(lane >> 4) << 4);
                LDX4(af[mt], aaddr);
            }
#pragma unroll
            for (int np = 0; np < 4; np++) {
                int rn = nbase + np * 16 + (lane & 7) + ((lane >> 1) & 8);
                u32 baddr = sb + off + T_B + (u32)rn * RSTR + (u32)ks * 32
                          + (((u32)(lane >> 3) & 1) << 4);
                u32 bf[4];
                LDX4(bf, baddr);
#pragma unroll
                for (int h = 0; h < 2; h++) {
                    int nt = np * 2 + h;
#pragma unroll
                    for (int mt = 0; mt < 2; mt++)
                        MMA(acc[mt][nt], af[mt], bf[2 * h], bf[2 * h + 1]);
                }
            }
        }
        // trailing barrier elided: next stsA targets the other buffer, whose
        // readers all passed this chunk's barrier after finishing its compute.
    }

    // Epilogue: bias + store (k,b,t,o)
#pragma unroll
    for (int mt = 0; mt < 2; mt++) {
        int m0 = mbase + mt * 16 + (lane >> 2);
        float* base0 = g_scr + ((size_t)(k * BATCH + b) * TLEN + t0 + m0) * OC;
        float* base1 = base0 + 8 * OC;
#pragma unroll
        for (int nt = 0; nt < 8; nt++) {
            int o0 = nbase + nt * 8 + (lane & 3) * 2;
            float2 bb = *(float2*)(bias_s + o0);
            float2 v0, v1;
            v0.x = acc[mt][nt][0] + bb.x; v0.y = acc[mt][nt][1] + bb.y;
            v1.x = acc[mt][nt][2] + bb.x; v1.y = acc[mt][nt][3] + bb.y;
            *(float2*)(base0 + o0) = v0;
            *(float2*)(base1 + o0) = v1;
        }
    }
}

// ---------------------------------------------------------------------------
// Transpose (k,b,t,o) -> (b,o,t,k)
// ---------------------------------------------------------------------------
__global__ __launch_bounds__(256) void trans_kernel(float* __restrict__ out) {
    __shared__ float sm[NB][OC + 1];
    int t = blockIdx.x, b = blockIdx.y, tid = threadIdx.x;
    const float* src = g_scr + ((size_t)b * TLEN + t) * OC;
#pragma unroll
    for (int i = 0; i < 32; i++) {
        int e = tid + i * 256;
        int kk = e >> 7, o = e & 127;
        sm[kk][o] = src[(size_t)kk * (BATCH * TLEN * OC) + o];
    }
    __syncthreads();
    float* dst = out + ((size_t)b * OC) * (TLEN * (size_t)NB) + (size_t)t * NB;
#pragma unroll
    for (int i = 0; i < 32; i++) {
        int e = tid + i * 256;
        int o = e >> 6, kk = e & 63;
        dst[(size_t)o * (TLEN * NB) + kk] = sm[kk][o];
    }
}

// ---------------------------------------------------------------------------
extern "C" void kernel_launch(void* const* d_in, const int* in_sizes, int n_in,
                              void* d_out, int out_size) {
    const float* x     = (const float*)d_in[0];
    const int*   idx   = (const int*)  d_in[1];
    const float* mel_w = (const float*)d_in[2];
    const float* pre_w = (const float*)d_in[3];
    const float* pre_b = (const float*)d_in[4];
    float* out = (float*)d_out;

    int W = in_sizes[1] / NB;
    int KTOT = 2 * W;
    int nCh = (KTOT + KC - 1) / KC;
    int KKPAD = nCh * KC;

    cudaFuncSetAttribute(gemm_mma, cudaFuncAttributeMaxDynamicSharedMemorySize, SM_BYTES);

    prepB<<<dim3(nCh, NB), 256>>>(pre_w, mel_w, W, KTOT, KKPAD);
    gemm_mma<<<dim3(TLEN / TM, BATCH, NB), 256, SM_BYTES>>>(x, idx, pre_b,
                                                            W, KTOT, nCh, KKPAD);
    trans_kernel<<<dim3(TLEN, BATCH), 256>>>(out);
}

// round 14
// speedup vs baseline: 1.7992x; 1.0648x over previous
#include <cuda_runtime.h>
#include <cuda_fp16.h>
#include <cstdint>

// Problem constants
#define NB     64
#define OC     128
#define BATCH  4
#define TLEN   1024
#define FBINS  1025
#define TM     128     // t rows per CTA
#define KC     32      // K per smem buffer (2 x m16n8k16 steps)

// Smem: 2 tiles per buffer (A, B), 128 rows x 80B (64B data + 16B pad).
// RSTR=80: 16B-aligned rows, ldmatrix conflict-free (20r mod 32 distinct).
#define RSTR   80
#define BUFSZ  20480            // 2 tiles x 128 x 80
#define T_A    0
#define T_B    10240
#define SM_IDX 40960            // int[192]
#define SM_BIAS 41728           // float[128]
#define SM_BYTES 42240

// Device scratch
__device__ float    g_scr[NB * BATCH * TLEN * OC];  // (k,b,t,o)
__device__ unsigned g_b16[NB * OC * 256];           // B' fp16 [k][o][kkpad], u32 pairs

typedef unsigned u32;

__device__ __forceinline__ u32 smem_u32(const void* p) {
    u32 a;
    asm("{ .reg .u64 t; cvta.to.shared.u64 t, %1; cvt.u32.u64 %0, t; }" : "=r"(a) : "l"(p));
    return a;
}
__device__ __forceinline__ void cp16(u32 dst, const void* src) {
    asm volatile("cp.async.cg.shared.global [%0], [%1], 16;" :: "r"(dst), "l"(src) : "memory");
}
__device__ __forceinline__ void cp_commit() { asm volatile("cp.async.commit_group;" ::: "memory"); }
__device__ __forceinline__ void cp_wait0()  { asm volatile("cp.async.wait_group 0;" ::: "memory"); }

#define LDX4(r, addr) \
    asm volatile("ldmatrix.sync.aligned.m8n8.x4.shared.b16 {%0,%1,%2,%3}, [%4];" \
        : "=r"((r)[0]), "=r"((r)[1]), "=r"((r)[2]), "=r"((r)[3]) : "r"(addr))

#define MMA(d, A, b0, b1) \
    asm volatile("mma.sync.aligned.m16n8k16.row.col.f32.f16.f16.f32 " \
        "{%0,%1,%2,%3}, {%4,%5,%6,%7}, {%8,%9}, {%0,%1,%2,%3};" \
        : "+f"((d)[0]), "+f"((d)[1]), "+f"((d)[2]), "+f"((d)[3]) \
        : "r"((A)[0]), "r"((A)[1]), "r"((A)[2]), "r"((A)[3]), "r"(b0), "r"(b1))

// ---------------------------------------------------------------------------
// prepB: B'[k][o][kk] = fp16(mel[k][w] * pre_w[k][c][w][o]),  kk = c*W + w.
// 32kk x 32o tiles, grid (nCh, NB, 4): 2048 blocks for latency hiding.
// ---------------------------------------------------------------------------
__global__ __launch_bounds__(256) void prepB(const float* __restrict__ pre_w,
                                             const float* __restrict__ mel_w,
                                             int W, int KTOT, int KKPAD) {
    __shared__ float tile[32][33];
    int ch = blockIdx.x, k = blockIdx.y, og = blockIdx.z, tid = threadIdx.x;
#pragma unroll
    for (int i = 0; i < 4; i++) {
        int e = tid + i * 256;             // 0..1023
        int kkL = e >> 5, oL = e & 31;
        int kkg = ch * 32 + kkL;
        float v = 0.f;
        if (kkg < KTOT) {
            int c = (kkg >= W), w = kkg - (c ? W : 0);
            v = mel_w[k * W + w] * pre_w[((size_t)(k * 2 + c) * W + w) * OC + og * 32 + oL];
        }
        tile[kkL][oL] = v;
    }
    __syncthreads();
    unsigned short* bp = (unsigned short*)g_b16;
#pragma unroll
    for (int i = 0; i < 4; i++) {
        int e = tid + i * 256;
        int oL = e >> 5, kkL = e & 31;
        bp[(size_t)(k * OC + og * 32 + oL) * KKPAD + ch * 32 + kkL] =
            __half_as_ushort(__float2half_rn(tile[kkL][oL]));
    }
}

// ---------------------------------------------------------------------------
// Tensor-core band GEMM, single fp16 term: D = fp16(A) * fp16(mel*W).
// CTA (k, b, t-tile 128); 8 warps 4x2; warp tile 32x64; KC=32, 1 barrier/chunk.
// A: pure fp32 LDGs issued pre-MMA (latency hidden under MMA phase); the
//    fp16 convert+pack runs at NEXT-chunk sts time, after the loads landed.
// B: pre-converted + mel-folded, via cp.async.
// ---------------------------------------------------------------------------
__global__ __launch_bounds__(256, 2) void gemm_mma(
    const float* __restrict__ x, const int* __restrict__ idx,
    const float* __restrict__ bias, int W, int KTOT, int nChunks, int KKPAD) {
    extern __shared__ char smem[];
    const u32 sb = smem_u32(smem);
    const int tid = threadIdx.x, wid = tid >> 5, lane = tid & 31;
    const int k = blockIdx.z, b = blockIdx.y, t0 = blockIdx.x * TM;
    const int wm = wid >> 1, wn = wid & 1;
    const int mbase = wm * 32, nbase = wn * 64;

    int*   idx_s  = (int*)(smem + SM_IDX);
    float* bias_s = (float*)(smem + SM_BIAS);
    for (int e = tid; e < W; e += 256) idx_s[e] = idx[k * W + e];
    if (tid < 128) bias_s[tid] = bias[k * OC + tid];
    __syncthreads();

    const float* xb = x + (size_t)b * 2 * TLEN * FBINS;

    // --- A: thread owns col pair (2pr, 2pr+1), rows r0+16i; raw fp32 staged ---
    const int pr = tid & 15;
    const int r0 = tid >> 4;
    float aF0[8], aF1[8];
    auto loadA = [&](int ch) {     // pure loads, no dependent math
        int ke0 = ch * KC + 2 * pr, ke1 = ke0 + 1;
        int c0 = 0, f0 = 0, c1 = 0, f1 = 0;
        if (ke0 < KTOT) { c0 = (ke0 >= W); f0 = idx_s[ke0 - (c0 ? W : 0)]; }
        if (ke1 < KTOT) { c1 = (ke1 >= W); f1 = idx_s[ke1 - (c1 ? W : 0)]; }
        const float* p0 = xb + (size_t)(c0 * TLEN + t0 + r0) * FBINS + f0;
        const float* p1 = xb + (size_t)(c1 * TLEN + t0 + r0) * FBINS + f1;
#pragma unroll
        for (int i = 0; i < 8; i++) {
            size_t s = (size_t)i * 16 * FBINS;
            aF0[i] = p0[s];                // wide LDG.32, coalesced over lanes
            aF1[i] = p1[s];
        }
    };
    auto stsA = [&](u32 off) {     // convert + pack + STS (loads landed by now)
#pragma unroll
        for (int i = 0; i < 8; i++) {
            __half2 hv = __floats2half2_rn(aF0[i], aF1[i]);
            u32 ba = off + T_A + (u32)(r0 + 16 * i) * RSTR + (u32)pr * 4;
            *(u32*)(smem + ba) = *(u32*)&hv;
        }
    };
    // --- B: 2x cp.async 16B per thread per chunk ---
    const int oB = tid >> 1, segB = tid & 1;
    const size_t brow = (size_t)(k * OC + oB) * (KKPAD >> 1);
    auto issueB = [&](int ch, u32 off) {
        const u32* src = g_b16 + brow + ch * 16 + segB * 8;
        u32 dst = sb + off + T_B + (u32)oB * RSTR + (u32)segB * 32;
        cp16(dst, src);
        cp16(dst + 16, src + 4);
        cp_commit();
    };

    float acc[2][8][4];
#pragma unroll
    for (int mt = 0; mt < 2; mt++)
#pragma unroll
        for (int nt = 0; nt < 8; nt++)
#pragma unroll
            for (int j = 0; j < 4; j++) acc[mt][nt][j] = 0.f;

    issueB(0, 0);
    loadA(0);

    for (int ch = 0; ch < nChunks; ch++) {
        const u32 off = (u32)(ch & 1) * BUFSZ;
        stsA(off);
        cp_wait0();
        __syncthreads();                   // single barrier per chunk
        if (ch + 1 < nChunks) { issueB(ch + 1, off ^ BUFSZ); loadA(ch + 1); }

#pragma unroll
        for (int ks = 0; ks < 2; ks++) {
            u32 af[2][4];
#pragma unroll
            for (int mt = 0; mt < 2; mt++) {
                u32 aaddr = sb + off + T_A + (u32)(mbase + mt * 16 + (lane & 15)) * RSTR
                          + (u32)ks * 32 + ((u32)(lane >> 4) << 4);
                LDX4(af[mt], aaddr);
            }
#pragma unroll
            for (int np = 0; np < 4; np++) {
                int rn = nbase + np * 16 + (lane & 7) + ((lane >> 1) & 8);
                u32 baddr = sb + off + T_B + (u32)rn * RSTR + (u32)ks * 32
                          + (((u32)(lane >> 3) & 1) << 4);
                u32 bf[4];
                LDX4(bf, baddr);
#pragma unroll
                for (int h = 0; h < 2; h++) {
                    int nt = np * 2 + h;
#pragma unroll
                    for (int mt = 0; mt < 2; mt++)
                        MMA(acc[mt][nt], af[mt], bf[2 * h], bf[2 * h + 1]);
                }
            }
        }
        // trailing barrier elided: next stsA targets the other buffer, whose
        // readers all passed this chunk's barrier after finishing its compute.
    }

    // Epilogue: bias + store (k,b,t,o)
#pragma unroll
    for (int mt = 0; mt < 2; mt++) {
        int m0 = mbase + mt * 16 + (lane >> 2);
        float* base0 = g_scr + ((size_t)(k * BATCH + b) * TLEN + t0 + m0) * OC;
        float* base1 = base0 + 8 * OC;
#pragma unroll
        for (int nt = 0; nt < 8; nt++) {
            int o0 = nbase + nt * 8 + (lane & 3) * 2;
            float2 bb = *(float2*)(bias_s + o0);
            float2 v0, v1;
            v0.x = acc[mt][nt][0] + bb.x; v0.y = acc[mt][nt][1] + bb.y;
            v1.x = acc[mt][nt][2] + bb.x; v1.y = acc[mt][nt][3] + bb.y;
            *(float2*)(base0 + o0) = v0;
            *(float2*)(base1 + o0) = v1;
        }
    }
}

// ---------------------------------------------------------------------------
// Transpose (k,b,t,o) -> (b,o,t,k)
// ---------------------------------------------------------------------------
__global__ __launch_bounds__(256) void trans_kernel(float* __restrict__ out) {
    __shared__ float sm[NB][OC + 1];
    int t = blockIdx.x, b = blockIdx.y, tid = threadIdx.x;
    const float* src = g_scr + ((size_t)b * TLEN + t) * OC;
#pragma unroll
    for (int i = 0; i < 32; i++) {
        int e = tid + i * 256;
        int kk = e >> 7, o = e & 127;
        sm[kk][o] = src[(size_t)kk * (BATCH * TLEN * OC) + o];
    }
    __syncthreads();
    float* dst = out + ((size_t)b * OC) * (TLEN * (size_t)NB) + (size_t)t * NB;
#pragma unroll
    for (int i = 0; i < 32; i++) {
        int e = tid + i * 256;
        int o = e >> 6, kk = e & 63;
        dst[(size_t)o * (TLEN * NB) + kk] = sm[kk][o];
    }
}

// ---------------------------------------------------------------------------
extern "C" void kernel_launch(void* const* d_in, const int* in_sizes, int n_in,
                              void* d_out, int out_size) {
    const float* x     = (const float*)d_in[0];
    const int*   idx   = (const int*)  d_in[1];
    const float* mel_w = (const float*)d_in[2];
    const float* pre_w = (const float*)d_in[3];
    const float* pre_b = (const float*)d_in[4];
    float* out = (float*)d_out;

    int W = in_sizes[1] / NB;
    int KTOT = 2 * W;
    int nCh = (KTOT + KC - 1) / KC;
    int KKPAD = nCh * KC;

    cudaFuncSetAttribute(gemm_mma, cudaFuncAttributeMaxDynamicSharedMemorySize, SM_BYTES);

    prepB<<<dim3(nCh, NB, 4), 256>>>(pre_w, mel_w, W, KTOT, KKPAD);
    gemm_mma<<<dim3(TLEN / TM, BATCH, NB), 256, SM_BYTES>>>(x, idx, pre_b,
                                                            W, KTOT, nCh, KKPAD);
    trans_kernel<<<dim3(TLEN, BATCH), 256>>>(out);
}